// round 4
// baseline (speedup 1.0000x reference)
#include <cuda_runtime.h>
#include <cuda_bf16.h>
#include <stdint.h>

#define BB 64
#define TT 1024
#define DD 128
#define HH 512
#define ZZ 64
#define G4 2048
#define TB 65536
#define SPAD 520
#define GCTAS 64

// ---------------- static scratch ----------------
__device__ float          g_gx[(size_t)TB * G4];
__device__ __nv_bfloat16  g_hs[(size_t)TB * HH];      // decoder layer0/1 hidden seq (bf16)
__device__ __nv_bfloat16  g_hsh[(size_t)TB * HH];     // encoder layer0 hidden seq hi
__device__ __nv_bfloat16  g_hsl[(size_t)TB * HH];     // encoder layer0 hidden seq lo
__device__ __nv_bfloat16  g_xth[(size_t)TB * DD];     // x transposed [T,B,D] hi
__device__ __nv_bfloat16  g_xtl[(size_t)TB * DD];     // lo
__device__ __nv_bfloat16  g_whh[2][(size_t)G4 * HH];  // decoder Whh bf16 (dec0, dec1)
__device__ __nv_bfloat16  g_wih0h[G4 * DD];           // enc Wih0 hi/lo
__device__ __nv_bfloat16  g_wih0l[G4 * DD];
__device__ __nv_bfloat16  g_wih1h[(size_t)G4 * HH];   // enc Wih1 hi/lo
__device__ __nv_bfloat16  g_wih1l[(size_t)G4 * HH];
__device__ __nv_bfloat16  g_wih1d[(size_t)G4 * HH];   // dec Wih1 bf16
__device__ __nv_bfloat16  g_opw[DD * HH];
__device__ float          g_bsum[4][G4];
__device__ __nv_bfloat16  g_hcur[2][BB * HH];         // decoder state ping-pong (bf16)
__device__ __nv_bfloat16  g_ehi[2][BB * HH];          // encoder state hi planes
__device__ __nv_bfloat16  g_elo[2][BB * HH];          // encoder state lo planes
__device__ float          g_M[BB * 2 * HH];
__device__ float          g_zbuf[BB * ZZ];
__device__ unsigned       g_barCnt;
__device__ unsigned       g_barGen;

__device__ __forceinline__ float fsig(float x)  { return __fdividef(1.f, 1.f + __expf(-x)); }
__device__ __forceinline__ float ftanhx(float x){ return 1.f - __fdividef(2.f, __expf(2.f * x) + 1.f); }

__device__ __forceinline__ unsigned bar_arrive() {
    __threadfence();
    __syncthreads();
    unsigned gen = 0u;
    if (threadIdx.x == 0) {
        gen = *(volatile unsigned*)&g_barGen;
        unsigned a = atomicAdd(&g_barCnt, 1u);
        if (a == GCTAS - 1u) {
            *(volatile unsigned*)&g_barCnt = 0u;
            __threadfence();
            *(volatile unsigned*)&g_barGen = gen + 1u;
        }
    }
    return gen;
}
__device__ __forceinline__ void bar_wait(unsigned gen) {
    if (threadIdx.x == 0) {
        while (*(volatile unsigned*)&g_barGen == gen) { }
        __threadfence();
    }
    __syncthreads();
}

#define MMA_BF16(ACC, A0,A1,A2,A3, B0,B1) \
    asm volatile( \
        "mma.sync.aligned.m16n8k16.row.col.f32.bf16.bf16.f32 " \
        "{%0,%1,%2,%3}, {%4,%5,%6,%7}, {%8,%9}, {%0,%1,%2,%3};\n" \
        : "+f"(ACC[0]), "+f"(ACC[1]), "+f"(ACC[2]), "+f"(ACC[3]) \
        : "r"(A0), "r"(A1), "r"(A2), "r"(A3), "r"(B0), "r"(B1))

// ================= split-bf16 encoder LSTM scan =================
// State as hi/lo bf16 planes (exact fp32-pair). 3-term MMA per gate.
__global__ void __launch_bounds__(128, 1) lstm_scan_split_kernel(
    const float* __restrict__ Whh,           // [2048][512] fp32
    const float* __restrict__ gx,            // [T*B][2048] fp32
    __nv_bfloat16* __restrict__ hs_hi,       // [T*B][512] or null
    __nv_bfloat16* __restrict__ hs_lo)
{
    extern __shared__ __nv_bfloat16 sm[];
    __nv_bfloat16* Wh = sm;                   // [32][SPAD]
    __nv_bfloat16* Wl = sm + 32 * SPAD;       // [32][SPAD]
    __nv_bfloat16* Hh = sm + 64 * SPAD;       // [64][SPAD]
    __nv_bfloat16* Hl = sm + 128 * SPAD;      // [64][SPAD]
    const int tid  = threadIdx.x;
    const int ci   = blockIdx.x;
    const int j0   = ci * 8;
    const int warp = tid >> 5, lane = tid & 31;
    const int qr   = lane >> 2, qc = lane & 3;
    const int r0   = warp * 16 + qr;

    // split Whh slice into hi/lo smem tiles
    for (int idx = tid; idx < 32 * 128; idx += 128) {
        int rl = idx >> 7, c4 = (idx & 127) << 2;
        int gi = rl >> 3, jj = rl & 7;
        float4 v = *(const float4*)(Whh + (size_t)(gi * 512 + j0 + jj) * 512 + c4);
        __nv_bfloat16 h0v = __float2bfloat16_rn(v.x);
        __nv_bfloat16 h1v = __float2bfloat16_rn(v.y);
        __nv_bfloat16 h2v = __float2bfloat16_rn(v.z);
        __nv_bfloat16 h3v = __float2bfloat16_rn(v.w);
        __nv_bfloat16 l0v = __float2bfloat16_rn(v.x - __bfloat162float(h0v));
        __nv_bfloat16 l1v = __float2bfloat16_rn(v.y - __bfloat162float(h1v));
        __nv_bfloat16 l2v = __float2bfloat16_rn(v.z - __bfloat162float(h2v));
        __nv_bfloat16 l3v = __float2bfloat16_rn(v.w - __bfloat162float(h3v));
        __nv_bfloat16* ph = Wh + rl * SPAD + c4;
        __nv_bfloat16* pl = Wl + rl * SPAD + c4;
        ph[0] = h0v; ph[1] = h1v; ph[2] = h2v; ph[3] = h3v;
        pl[0] = l0v; pl[1] = l1v; pl[2] = l2v; pl[3] = l3v;
    }
    // zero-init state slice in buffer 0
    for (int idx = tid; idx < 512; idx += 128) {
        int r = idx >> 3, jj = idx & 7;
        unsigned short z = 0;
        asm volatile("st.global.cg.u16 [%0], %1;" :: "l"(g_ehi[0] + r * 512 + j0 + jj), "h"(z));
        asm volatile("st.global.cg.u16 [%0], %1;" :: "l"(g_elo[0] + r * 512 + j0 + jj), "h"(z));
    }
    float creg[4] = {0.f, 0.f, 0.f, 0.f};
    float acc[4][4];

    unsigned tok = bar_arrive();
    #pragma unroll
    for (int i = 0; i < 4; ++i) {
        int col = i * 512 + j0 + qc * 2;
        float2 lo = *(const float2*)(gx + (size_t)r0       * 2048 + col);
        float2 hi = *(const float2*)(gx + (size_t)(r0 + 8) * 2048 + col);
        acc[i][0] = lo.x; acc[i][1] = lo.y; acc[i][2] = hi.x; acc[i][3] = hi.y;
    }
    bar_wait(tok);

    for (int t = 0; t < TT; ++t) {
        const __nv_bfloat16* rbh = g_ehi[t & 1];
        const __nv_bfloat16* rbl = g_elo[t & 1];
        __nv_bfloat16* wbh = g_ehi[(t + 1) & 1];
        __nv_bfloat16* wbl = g_elo[(t + 1) & 1];

        for (int idx = tid; idx < 64 * 64; idx += 128) {
            int r = idx >> 6, c8 = (idx & 63) << 3;
            uint4 v;
            asm volatile("ld.global.cg.v4.u32 {%0,%1,%2,%3}, [%4];"
                : "=r"(v.x), "=r"(v.y), "=r"(v.z), "=r"(v.w) : "l"(rbh + r * 512 + c8));
            *(uint4*)(Hh + r * SPAD + c8) = v;
            asm volatile("ld.global.cg.v4.u32 {%0,%1,%2,%3}, [%4];"
                : "=r"(v.x), "=r"(v.y), "=r"(v.z), "=r"(v.w) : "l"(rbl + r * 512 + c8));
            *(uint4*)(Hl + r * SPAD + c8) = v;
        }
        __syncthreads();

        #pragma unroll
        for (int kt = 0; kt < 32; ++kt) {
            const int k0 = kt * 16 + qc * 2;
            uint32_t ah0 = *(const uint32_t*)(Hh + r0 * SPAD + k0);
            uint32_t ah1 = *(const uint32_t*)(Hh + (r0 + 8) * SPAD + k0);
            uint32_t ah2 = *(const uint32_t*)(Hh + r0 * SPAD + k0 + 8);
            uint32_t ah3 = *(const uint32_t*)(Hh + (r0 + 8) * SPAD + k0 + 8);
            uint32_t al0 = *(const uint32_t*)(Hl + r0 * SPAD + k0);
            uint32_t al1 = *(const uint32_t*)(Hl + (r0 + 8) * SPAD + k0);
            uint32_t al2 = *(const uint32_t*)(Hl + r0 * SPAD + k0 + 8);
            uint32_t al3 = *(const uint32_t*)(Hl + (r0 + 8) * SPAD + k0 + 8);
            #pragma unroll
            for (int i = 0; i < 4; ++i) {
                uint32_t bh0 = *(const uint32_t*)(Wh + (i * 8 + qr) * SPAD + k0);
                uint32_t bh1 = *(const uint32_t*)(Wh + (i * 8 + qr) * SPAD + k0 + 8);
                uint32_t bl0 = *(const uint32_t*)(Wl + (i * 8 + qr) * SPAD + k0);
                uint32_t bl1 = *(const uint32_t*)(Wl + (i * 8 + qr) * SPAD + k0 + 8);
                MMA_BF16(acc[i], ah0, ah1, ah2, ah3, bh0, bh1);
                MMA_BF16(acc[i], ah0, ah1, ah2, ah3, bl0, bl1);
                MMA_BF16(acc[i], al0, al1, al2, al3, bh0, bh1);
            }
        }

        float hv[4];
        #pragma unroll
        for (int k = 0; k < 4; ++k) {
            float ig = fsig(acc[0][k]);
            float fg = fsig(acc[1][k]);
            float gg = ftanhx(acc[2][k]);
            float og = fsig(acc[3][k]);
            creg[k] = fg * creg[k] + ig * gg;
            hv[k]   = og * ftanhx(creg[k]);
        }
        __nv_bfloat16 hh[4], hl[4];
        #pragma unroll
        for (int k = 0; k < 4; ++k) {
            hh[k] = __float2bfloat16_rn(hv[k]);
            hl[k] = __float2bfloat16_rn(hv[k] - __bfloat162float(hh[k]));
        }
        uint32_t ph0 = ((uint32_t)*(unsigned short*)&hh[1] << 16) | *(unsigned short*)&hh[0];
        uint32_t ph1 = ((uint32_t)*(unsigned short*)&hh[3] << 16) | *(unsigned short*)&hh[2];
        uint32_t pl0 = ((uint32_t)*(unsigned short*)&hl[1] << 16) | *(unsigned short*)&hl[0];
        uint32_t pl1 = ((uint32_t)*(unsigned short*)&hl[3] << 16) | *(unsigned short*)&hl[2];
        const int cbase = j0 + qc * 2;
        asm volatile("st.global.cg.u32 [%0], %1;" :: "l"(wbh + r0 * 512 + cbase), "r"(ph0));
        asm volatile("st.global.cg.u32 [%0], %1;" :: "l"(wbh + (r0 + 8) * 512 + cbase), "r"(ph1));
        asm volatile("st.global.cg.u32 [%0], %1;" :: "l"(wbl + r0 * 512 + cbase), "r"(pl0));
        asm volatile("st.global.cg.u32 [%0], %1;" :: "l"(wbl + (r0 + 8) * 512 + cbase), "r"(pl1));
        if (hs_hi) {
            *(uint32_t*)(hs_hi + (size_t)(t * 64 + r0)     * 512 + cbase) = ph0;
            *(uint32_t*)(hs_hi + (size_t)(t * 64 + r0 + 8) * 512 + cbase) = ph1;
            *(uint32_t*)(hs_lo + (size_t)(t * 64 + r0)     * 512 + cbase) = pl0;
            *(uint32_t*)(hs_lo + (size_t)(t * 64 + r0 + 8) * 512 + cbase) = pl1;
        }

        tok = bar_arrive();
        if (t + 1 < TT) {
            #pragma unroll
            for (int i = 0; i < 4; ++i) {
                int col = i * 512 + j0 + qc * 2;
                float2 lo = *(const float2*)(gx + (size_t)((t + 1) * 64 + r0)     * 2048 + col);
                float2 hi = *(const float2*)(gx + (size_t)((t + 1) * 64 + r0 + 8) * 2048 + col);
                acc[i][0] = lo.x; acc[i][1] = lo.y; acc[i][2] = hi.x; acc[i][3] = hi.y;
            }
        }
        bar_wait(tok);
    }
}

// ================= plain bf16 decoder LSTM scan (unchanged from R3) =================
__global__ void __launch_bounds__(128, 1) lstm_scan_kernel(
    const __nv_bfloat16* __restrict__ Whh,
    const float* __restrict__ gx,
    const float* __restrict__ bias,
    const float* __restrict__ h0,
    __nv_bfloat16* __restrict__ hs)
{
    extern __shared__ __nv_bfloat16 sm[];
    __nv_bfloat16* Ws = sm;
    __nv_bfloat16* Hb = sm + 32 * SPAD;
    const int tid  = threadIdx.x;
    const int ci   = blockIdx.x;
    const int j0   = ci * 8;
    const int warp = tid >> 5, lane = tid & 31;
    const int qr   = lane >> 2, qc = lane & 3;
    const int r0   = warp * 16 + qr;

    for (int idx = tid; idx < 32 * 64; idx += 128) {
        int rl = idx >> 6, c8 = (idx & 63) << 3;
        int gi = rl >> 3, jj = rl & 7;
        *(uint4*)(Ws + rl * SPAD + c8) =
            *(const uint4*)(Whh + (size_t)(gi * 512 + j0 + jj) * 512 + c8);
    }
    for (int idx = tid; idx < 512; idx += 128) {
        int r = idx >> 3, jj = idx & 7;
        float v = h0 ? h0[r * 512 + j0 + jj] : 0.f;
        __nv_bfloat16 bv = __float2bfloat16(v);
        unsigned short us = *(unsigned short*)&bv;
        asm volatile("st.global.cg.u16 [%0], %1;" ::
            "l"(g_hcur[0] + r * 512 + j0 + jj), "h"(us));
    }
    float creg[4] = {0.f, 0.f, 0.f, 0.f};
    float acc[4][4];

    unsigned tok = bar_arrive();
    #pragma unroll
    for (int i = 0; i < 4; ++i) {
        int col = i * 512 + j0 + qc * 2;
        if (gx) {
            float2 lo = *(const float2*)(gx + (size_t)r0       * 2048 + col);
            float2 hi = *(const float2*)(gx + (size_t)(r0 + 8) * 2048 + col);
            acc[i][0] = lo.x; acc[i][1] = lo.y; acc[i][2] = hi.x; acc[i][3] = hi.y;
        } else {
            float b0v = bias[col], b1v = bias[col + 1];
            acc[i][0] = b0v; acc[i][1] = b1v; acc[i][2] = b0v; acc[i][3] = b1v;
        }
    }
    bar_wait(tok);

    for (int t = 0; t < TT; ++t) {
        const __nv_bfloat16* rb = g_hcur[t & 1];
        __nv_bfloat16*       wb = g_hcur[(t + 1) & 1];

        for (int idx = tid; idx < 64 * 64; idx += 128) {
            int r = idx >> 6, c8 = (idx & 63) << 3;
            uint4 v;
            asm volatile("ld.global.cg.v4.u32 {%0,%1,%2,%3}, [%4];"
                : "=r"(v.x), "=r"(v.y), "=r"(v.z), "=r"(v.w) : "l"(rb + r * 512 + c8));
            *(uint4*)(Hb + r * SPAD + c8) = v;
        }
        __syncthreads();

        #pragma unroll
        for (int kt = 0; kt < 32; ++kt) {
            const int k0 = kt * 16 + qc * 2;
            uint32_t a0 = *(const uint32_t*)(Hb + r0 * SPAD + k0);
            uint32_t a1 = *(const uint32_t*)(Hb + (r0 + 8) * SPAD + k0);
            uint32_t a2 = *(const uint32_t*)(Hb + r0 * SPAD + k0 + 8);
            uint32_t a3 = *(const uint32_t*)(Hb + (r0 + 8) * SPAD + k0 + 8);
            #pragma unroll
            for (int i = 0; i < 4; ++i) {
                uint32_t b0 = *(const uint32_t*)(Ws + (i * 8 + qr) * SPAD + k0);
                uint32_t b1 = *(const uint32_t*)(Ws + (i * 8 + qr) * SPAD + k0 + 8);
                MMA_BF16(acc[i], a0, a1, a2, a3, b0, b1);
            }
        }

        float hv[4];
        #pragma unroll
        for (int k = 0; k < 4; ++k) {
            float ig = fsig(acc[0][k]);
            float fg = fsig(acc[1][k]);
            float gg = ftanhx(acc[2][k]);
            float og = fsig(acc[3][k]);
            creg[k] = fg * creg[k] + ig * gg;
            hv[k]   = og * ftanhx(creg[k]);
        }
        __nv_bfloat162 p0 = __floats2bfloat162_rn(hv[0], hv[1]);
        __nv_bfloat162 p1 = __floats2bfloat162_rn(hv[2], hv[3]);
        const int cbase = j0 + qc * 2;
        asm volatile("st.global.cg.u32 [%0], %1;" ::
            "l"(wb + r0 * 512 + cbase), "r"(*(uint32_t*)&p0));
        asm volatile("st.global.cg.u32 [%0], %1;" ::
            "l"(wb + (r0 + 8) * 512 + cbase), "r"(*(uint32_t*)&p1));
        if (hs) {
            *(__nv_bfloat162*)(hs + (size_t)(t * 64 + r0)     * 512 + cbase) = p0;
            *(__nv_bfloat162*)(hs + (size_t)(t * 64 + r0 + 8) * 512 + cbase) = p1;
        }

        tok = bar_arrive();
        if (t + 1 < TT) {
            const int tn = t + 1;
            #pragma unroll
            for (int i = 0; i < 4; ++i) {
                int col = i * 512 + j0 + qc * 2;
                if (gx) {
                    float2 lo = *(const float2*)(gx + (size_t)(tn * 64 + r0)     * 2048 + col);
                    float2 hi = *(const float2*)(gx + (size_t)(tn * 64 + r0 + 8) * 2048 + col);
                    acc[i][0] = lo.x; acc[i][1] = lo.y; acc[i][2] = hi.x; acc[i][3] = hi.y;
                } else {
                    float b0v = bias[col], b1v = bias[col + 1];
                    acc[i][0] = b0v; acc[i][1] = b1v; acc[i][2] = b0v; acc[i][3] = b1v;
                }
            }
        }
        bar_wait(tok);
    }
}

// ================= split-bf16 GEMM: C = Ah@Bh^T + Ah@Bl^T + Al@Bh^T + bias =================
__global__ void __launch_bounds__(256, 2) gemm_split_kernel(
    const __nv_bfloat16* __restrict__ Ah, const __nv_bfloat16* __restrict__ Al,
    const __nv_bfloat16* __restrict__ Bh, const __nv_bfloat16* __restrict__ Bl,
    const float* __restrict__ bias, float* __restrict__ Cout, int N, int K)
{
    __shared__ __nv_bfloat16 Ash[128 * 40];
    __shared__ __nv_bfloat16 Asl[128 * 40];
    __shared__ __nv_bfloat16 Bsh[64 * 40];
    __shared__ __nv_bfloat16 Bsl[64 * 40];
    const int tid  = threadIdx.x;
    const int warp = tid >> 5, lane = tid & 31;
    const int qr   = lane >> 2, qc = lane & 3;
    const int wm   = warp >> 1, wn = warp & 1;
    const int m0   = blockIdx.x * 128;
    const int n0   = blockIdx.y * 64;

    float acc[2][4][4];
    #pragma unroll
    for (int a = 0; a < 2; ++a)
        #pragma unroll
        for (int b = 0; b < 4; ++b)
            #pragma unroll
            for (int c = 0; c < 4; ++c) acc[a][b][c] = 0.f;

    for (int kt = 0; kt < K; kt += 32) {
        #pragma unroll
        for (int u = 0; u < 2; ++u) {
            int idx = tid + u * 256;
            int r = idx >> 2, c8 = (idx & 3) << 3;
            *(uint4*)(Ash + r * 40 + c8) = *(const uint4*)(Ah + (size_t)(m0 + r) * K + kt + c8);
            *(uint4*)(Asl + r * 40 + c8) = *(const uint4*)(Al + (size_t)(m0 + r) * K + kt + c8);
        }
        {
            int r = tid >> 2, c8 = (tid & 3) << 3;
            *(uint4*)(Bsh + r * 40 + c8) = *(const uint4*)(Bh + (size_t)(n0 + r) * K + kt + c8);
            *(uint4*)(Bsl + r * 40 + c8) = *(const uint4*)(Bl + (size_t)(n0 + r) * K + kt + c8);
        }
        __syncthreads();
        #pragma unroll
        for (int kk = 0; kk < 2; ++kk) {
            const int k0 = kk * 16 + qc * 2;
            #pragma unroll
            for (int mi = 0; mi < 2; ++mi) {
                int ar = wm * 32 + mi * 16 + qr;
                uint32_t ah0 = *(const uint32_t*)(Ash + ar * 40 + k0);
                uint32_t ah1 = *(const uint32_t*)(Ash + (ar + 8) * 40 + k0);
                uint32_t ah2 = *(const uint32_t*)(Ash + ar * 40 + k0 + 8);
                uint32_t ah3 = *(const uint32_t*)(Ash + (ar + 8) * 40 + k0 + 8);
                uint32_t al0 = *(const uint32_t*)(Asl + ar * 40 + k0);
                uint32_t al1 = *(const uint32_t*)(Asl + (ar + 8) * 40 + k0);
                uint32_t al2 = *(const uint32_t*)(Asl + ar * 40 + k0 + 8);
                uint32_t al3 = *(const uint32_t*)(Asl + (ar + 8) * 40 + k0 + 8);
                #pragma unroll
                for (int ni = 0; ni < 4; ++ni) {
                    int br = wn * 32 + ni * 8 + qr;
                    uint32_t bh0 = *(const uint32_t*)(Bsh + br * 40 + k0);
                    uint32_t bh1 = *(const uint32_t*)(Bsh + br * 40 + k0 + 8);
                    uint32_t bl0 = *(const uint32_t*)(Bsl + br * 40 + k0);
                    uint32_t bl1 = *(const uint32_t*)(Bsl + br * 40 + k0 + 8);
                    MMA_BF16(acc[mi][ni], ah0, ah1, ah2, ah3, bh0, bh1);
                    MMA_BF16(acc[mi][ni], ah0, ah1, ah2, ah3, bl0, bl1);
                    MMA_BF16(acc[mi][ni], al0, al1, al2, al3, bh0, bh1);
                }
            }
        }
        __syncthreads();
    }

    #pragma unroll
    for (int mi = 0; mi < 2; ++mi) {
        #pragma unroll
        for (int ni = 0; ni < 4; ++ni) {
            int gn = n0 + wn * 32 + ni * 8 + qc * 2;
            float bv0 = bias[gn], bv1 = bias[gn + 1];
            #pragma unroll
            for (int h = 0; h < 2; ++h) {
                int gm = m0 + wm * 32 + mi * 16 + qr + h * 8;
                *(float2*)(Cout + (size_t)gm * N + gn) =
                    make_float2(acc[mi][ni][h * 2 + 0] + bv0, acc[mi][ni][h * 2 + 1] + bv1);
            }
        }
    }
}

// ================= plain bf16 GEMM (decoder path, unchanged) =================
__global__ void __launch_bounds__(256, 2) gemm_bf16_kernel(
    const __nv_bfloat16* __restrict__ A,
    const __nv_bfloat16* __restrict__ Bw,
    const float* __restrict__ bias,
    float* __restrict__ Cout,
    int N, int K, int mode)
{
    __shared__ __nv_bfloat16 As[128 * 40];
    __shared__ __nv_bfloat16 Bs[64 * 40];
    const int tid  = threadIdx.x;
    const int warp = tid >> 5, lane = tid & 31;
    const int qr   = lane >> 2, qc = lane & 3;
    const int wm   = warp >> 1, wn = warp & 1;
    const int m0   = blockIdx.x * 128;
    const int n0   = blockIdx.y * 64;

    float acc[2][4][4];
    #pragma unroll
    for (int a = 0; a < 2; ++a)
        #pragma unroll
        for (int b = 0; b < 4; ++b)
            #pragma unroll
            for (int c = 0; c < 4; ++c) acc[a][b][c] = 0.f;

    for (int kt = 0; kt < K; kt += 32) {
        #pragma unroll
        for (int u = 0; u < 2; ++u) {
            int idx = tid + u * 256;
            int r = idx >> 2, c8 = (idx & 3) << 3;
            *(uint4*)(As + r * 40 + c8) = *(const uint4*)(A + (size_t)(m0 + r) * K + kt + c8);
        }
        {
            int r = tid >> 2, c8 = (tid & 3) << 3;
            *(uint4*)(Bs + r * 40 + c8) = *(const uint4*)(Bw + (size_t)(n0 + r) * K + kt + c8);
        }
        __syncthreads();
        #pragma unroll
        for (int kk = 0; kk < 2; ++kk) {
            const int k0 = kk * 16 + qc * 2;
            #pragma unroll
            for (int mi = 0; mi < 2; ++mi) {
                int ar = wm * 32 + mi * 16 + qr;
                uint32_t a0 = *(const uint32_t*)(As + ar * 40 + k0);
                uint32_t a1 = *(const uint32_t*)(As + (ar + 8) * 40 + k0);
                uint32_t a2 = *(const uint32_t*)(As + ar * 40 + k0 + 8);
                uint32_t a3 = *(const uint32_t*)(As + (ar + 8) * 40 + k0 + 8);
                #pragma unroll
                for (int ni = 0; ni < 4; ++ni) {
                    int br = wn * 32 + ni * 8 + qr;
                    uint32_t b0 = *(const uint32_t*)(Bs + br * 40 + k0);
                    uint32_t b1 = *(const uint32_t*)(Bs + br * 40 + k0 + 8);
                    MMA_BF16(acc[mi][ni], a0, a1, a2, a3, b0, b1);
                }
            }
        }
        __syncthreads();
    }

    #pragma unroll
    for (int mi = 0; mi < 2; ++mi) {
        #pragma unroll
        for (int ni = 0; ni < 4; ++ni) {
            int gn = n0 + wn * 32 + ni * 8 + qc * 2;
            float bv0 = bias[gn], bv1 = bias[gn + 1];
            #pragma unroll
            for (int h = 0; h < 2; ++h) {
                int gm = m0 + wm * 32 + mi * 16 + qr + h * 8;
                float v0 = acc[mi][ni][h * 2 + 0] + bv0;
                float v1 = acc[mi][ni][h * 2 + 1] + bv1;
                if (mode == 1) {
                    int tt = gm >> 6, bb = gm & 63;
                    *(float2*)(Cout + ((size_t)bb * TT + tt) * DD + gn) =
                        make_float2(fsig(v0), fsig(v1));
                } else {
                    *(float2*)(Cout + (size_t)gm * N + gn) = make_float2(v0, v1);
                }
            }
        }
    }
}

// ================= helpers =================
__global__ void cvt_bf16_kernel(const float* __restrict__ s, __nv_bfloat16* __restrict__ d, int n) {
    int i = blockIdx.x * blockDim.x + threadIdx.x;
    if (i < n) d[i] = __float2bfloat16(s[i]);
}
__global__ void split_w_kernel(const float* __restrict__ s,
                               __nv_bfloat16* __restrict__ hi, __nv_bfloat16* __restrict__ lo, int n) {
    int i = blockIdx.x * blockDim.x + threadIdx.x;
    if (i < n) {
        float v = s[i];
        __nv_bfloat16 h = __float2bfloat16_rn(v);
        hi[i] = h;
        lo[i] = __float2bfloat16_rn(v - __bfloat162float(h));
    }
}
__global__ void bias_sum_kernel(const float* __restrict__ a, const float* __restrict__ b,
                                float* __restrict__ d, int n) {
    int i = blockIdx.x * blockDim.x + threadIdx.x;
    if (i < n) d[i] = a[i] + b[i];
}
__global__ void transpose_split_kernel(const float* __restrict__ x,
                                       __nv_bfloat16* __restrict__ xh, __nv_bfloat16* __restrict__ xl) {
    int i = blockIdx.x * blockDim.x + threadIdx.x;
    if (i < TB * DD) {
        int d = i & (DD - 1);
        int r = i >> 7;
        int b = r & 63, t = r >> 6;
        float v = x[((size_t)b * TT + t) * DD + d];
        __nv_bfloat16 h = __float2bfloat16_rn(v);
        xh[i] = h;
        xl[i] = __float2bfloat16_rn(v - __bfloat162float(h));
    }
}
__global__ void z_kernel(const float* __restrict__ tlW, const float* __restrict__ tlb,
                         float* __restrict__ zout) {
    int idx = blockIdx.x * blockDim.x + threadIdx.x;
    if (idx < BB * ZZ) {
        int b = idx >> 6, j = idx & 63;
        float s = 0.f;
        for (int k = 0; k < 512; ++k) {
            float hv = __bfloat162float(g_ehi[0][b * 512 + k]) +
                       __bfloat162float(g_elo[0][b * 512 + k]);
            s += hv * tlW[j * 512 + k];
        }
        s += tlb[j];
        g_zbuf[idx] = s;
        zout[idx] = s;
    }
}
__global__ void m_kernel(const float* __restrict__ lhW, const float* __restrict__ lhb) {
    int b = blockIdx.x, k1 = threadIdx.x;
    float s = 0.f;
    for (int j = 0; j < 64; ++j)
        s += g_zbuf[b * 64 + j] * lhW[k1 * 64 + j];
    g_M[b * 1024 + k1] = tanhf(s + lhb[k1]);
}

extern "C" void kernel_launch(void* const* d_in, const int* in_sizes, int n_in,
                              void* d_out, int out_size) {
    const float* x     = (const float*)d_in[0];
    const float* eWih0 = (const float*)d_in[1];
    const float* eWhh0 = (const float*)d_in[2];
    const float* ebih0 = (const float*)d_in[3];
    const float* ebhh0 = (const float*)d_in[4];
    const float* eWih1 = (const float*)d_in[5];
    const float* eWhh1 = (const float*)d_in[6];
    const float* ebih1 = (const float*)d_in[7];
    const float* ebhh1 = (const float*)d_in[8];
    const float* dWhh0 = (const float*)d_in[10];
    const float* dbih0 = (const float*)d_in[11];
    const float* dbhh0 = (const float*)d_in[12];
    const float* dWih1 = (const float*)d_in[13];
    const float* dWhh1 = (const float*)d_in[14];
    const float* dbih1 = (const float*)d_in[15];
    const float* dbhh1 = (const float*)d_in[16];
    const float* tlW   = (const float*)d_in[17];
    const float* tlb   = (const float*)d_in[18];
    const float* lhW   = (const float*)d_in[19];
    const float* lhb   = (const float*)d_in[20];
    const float* opW   = (const float*)d_in[21];
    const float* opb   = (const float*)d_in[22];
    float* out = (float*)d_out;

    __nv_bfloat16 *p_xth, *p_xtl, *p_whh0, *p_whh1;
    __nv_bfloat16 *p_w0h, *p_w0l, *p_w1h, *p_w1l, *p_wih1d, *p_opw;
    __nv_bfloat16 *p_hs, *p_hsh, *p_hsl;
    float *p_gx, *p_bs, *p_M;
    cudaGetSymbolAddress((void**)&p_xth, g_xth);
    cudaGetSymbolAddress((void**)&p_xtl, g_xtl);
    cudaGetSymbolAddress((void**)&p_gx, g_gx);
    cudaGetSymbolAddress((void**)&p_hs, g_hs);
    cudaGetSymbolAddress((void**)&p_hsh, g_hsh);
    cudaGetSymbolAddress((void**)&p_hsl, g_hsl);
    cudaGetSymbolAddress((void**)&p_bs, g_bsum);
    cudaGetSymbolAddress((void**)&p_M,  g_M);
    cudaGetSymbolAddress((void**)&p_w0h, g_wih0h);
    cudaGetSymbolAddress((void**)&p_w0l, g_wih0l);
    cudaGetSymbolAddress((void**)&p_w1h, g_wih1h);
    cudaGetSymbolAddress((void**)&p_w1l, g_wih1l);
    cudaGetSymbolAddress((void**)&p_wih1d, g_wih1d);
    cudaGetSymbolAddress((void**)&p_opw, g_opw);
    {
        __nv_bfloat16* base;
        cudaGetSymbolAddress((void**)&base, g_whh);
        p_whh0 = base;
        p_whh1 = base + (size_t)G4 * HH;
    }

    const int SPLIT_SMEM = 192 * SPAD * 2;   // 199,680 B
    const int DEC_SMEM   = 96 * SPAD * 2;    //  99,840 B
    cudaFuncSetAttribute(lstm_scan_split_kernel,
        cudaFuncAttributeMaxDynamicSharedMemorySize, SPLIT_SMEM);
    cudaFuncSetAttribute(lstm_scan_kernel,
        cudaFuncAttributeMaxDynamicSharedMemorySize, DEC_SMEM);

    const int CV = 256;
    // prep: splits for encoder, bf16 converts for decoder
    split_w_kernel<<<(G4*DD + CV-1)/CV, CV>>>(eWih0, p_w0h, p_w0l, G4*DD);
    split_w_kernel<<<(G4*HH + CV-1)/CV, CV>>>(eWih1, p_w1h, p_w1l, G4*HH);
    cvt_bf16_kernel<<<(G4*HH + CV-1)/CV, CV>>>(dWhh0, p_whh0, G4*HH);
    cvt_bf16_kernel<<<(G4*HH + CV-1)/CV, CV>>>(dWih1, p_wih1d, G4*HH);
    cvt_bf16_kernel<<<(G4*HH + CV-1)/CV, CV>>>(dWhh1, p_whh1, G4*HH);
    cvt_bf16_kernel<<<(DD*HH + CV-1)/CV, CV>>>(opW, p_opw, DD*HH);
    bias_sum_kernel<<<8, CV>>>(ebih0, ebhh0, p_bs + 0*G4, G4);
    bias_sum_kernel<<<8, CV>>>(ebih1, ebhh1, p_bs + 1*G4, G4);
    bias_sum_kernel<<<8, CV>>>(dbih0, dbhh0, p_bs + 2*G4, G4);
    bias_sum_kernel<<<8, CV>>>(dbih1, dbhh1, p_bs + 3*G4, G4);
    transpose_split_kernel<<<(TB*DD + CV-1)/CV, CV>>>(x, p_xth, p_xtl);

    dim3 gemm_grid(TB/128, G4/64);

    // ---- encoder (split precision) ----
    gemm_split_kernel<<<gemm_grid, 256>>>(p_xth, p_xtl, p_w0h, p_w0l, p_bs + 0*G4, p_gx, G4, DD);
    lstm_scan_split_kernel<<<GCTAS, 128, SPLIT_SMEM>>>(eWhh0, p_gx, p_hsh, p_hsl);
    gemm_split_kernel<<<gemm_grid, 256>>>(p_hsh, p_hsl, p_w1h, p_w1l, p_bs + 1*G4, p_gx, G4, HH);
    lstm_scan_split_kernel<<<GCTAS, 128, SPLIT_SMEM>>>(eWhh1, p_gx, nullptr, nullptr);

    // ---- latent ----
    z_kernel<<<(BB*ZZ + 255)/256, 256>>>(tlW, tlb, out + (size_t)BB*TT*DD);
    m_kernel<<<BB, 1024>>>(lhW, lhb);

    // ---- decoder (plain bf16) ----
    lstm_scan_kernel<<<GCTAS, 128, DEC_SMEM>>>(p_whh0, nullptr, p_bs + 2*G4, p_M, p_hs);
    gemm_bf16_kernel<<<gemm_grid, 256>>>(p_hs, p_wih1d, p_bs + 3*G4, p_gx, G4, HH, 0);
    lstm_scan_kernel<<<GCTAS, 128, DEC_SMEM>>>(p_whh1, p_gx, nullptr, p_M + 32768, p_hs);

    // ---- output projection + sigmoid ----
    dim3 op_grid(TB/128, DD/64);
    gemm_bf16_kernel<<<op_grid, 256>>>(p_hs, p_opw, opb, out, DD, HH, 1);
}

// round 5
// speedup vs baseline: 1.6319x; 1.6319x over previous
#include <cuda_runtime.h>
#include <cuda_bf16.h>
#include <stdint.h>

#define BB 64
#define TT 1024
#define DD 128
#define HH 512
#define ZZ 64
#define G4 2048
#define TB 65536
#define SPAD 520
#define GCTAS 64
#define NT 256

// ---------------- static scratch ----------------
__device__ float          g_gx[(size_t)TB * G4];
__device__ __nv_bfloat16  g_hs[(size_t)TB * HH];
__device__ __nv_bfloat16  g_hsh[(size_t)TB * HH];
__device__ __nv_bfloat16  g_hsl[(size_t)TB * HH];
__device__ __nv_bfloat16  g_xth[(size_t)TB * DD];
__device__ __nv_bfloat16  g_xtl[(size_t)TB * DD];
__device__ __nv_bfloat16  g_whh[2][(size_t)G4 * HH];
__device__ __nv_bfloat16  g_wih0h[G4 * DD];
__device__ __nv_bfloat16  g_wih0l[G4 * DD];
__device__ __nv_bfloat16  g_wih1h[(size_t)G4 * HH];
__device__ __nv_bfloat16  g_wih1l[(size_t)G4 * HH];
__device__ __nv_bfloat16  g_wih1d[(size_t)G4 * HH];
__device__ __nv_bfloat16  g_opw[DD * HH];
__device__ float          g_bsum[4][G4];
__device__ __nv_bfloat16  g_hcur[2][BB * HH];
__device__ __nv_bfloat16  g_ehi[2][BB * HH];
__device__ __nv_bfloat16  g_elo[2][BB * HH];
__device__ float          g_M[BB * 2 * HH];
__device__ float          g_zbuf[BB * ZZ];
__device__ unsigned       g_barCnt;
__device__ unsigned       g_barGen;

__device__ __forceinline__ float fsig(float x)  { return __fdividef(1.f, 1.f + __expf(-x)); }
__device__ __forceinline__ float ftanhx(float x){ return 1.f - __fdividef(2.f, __expf(2.f * x) + 1.f); }

// grid barrier (CG grid.sync pattern: bar.sync, then thread0 fence+atomic)
__device__ __forceinline__ unsigned bar_arrive() {
    __syncthreads();
    unsigned gen = 0u;
    if (threadIdx.x == 0) {
        __threadfence();
        gen = *(volatile unsigned*)&g_barGen;
        unsigned a = atomicAdd(&g_barCnt, 1u);
        if (a == GCTAS - 1u) {
            *(volatile unsigned*)&g_barCnt = 0u;
            __threadfence();
            *(volatile unsigned*)&g_barGen = gen + 1u;
        }
    }
    return gen;
}
__device__ __forceinline__ void bar_wait(unsigned gen) {
    if (threadIdx.x == 0) {
        while (*(volatile unsigned*)&g_barGen == gen) { }
        __threadfence();
    }
    __syncthreads();
}

#define MMA_BF16(ACC, A0,A1,A2,A3, B0,B1) \
    asm volatile( \
        "mma.sync.aligned.m16n8k16.row.col.f32.bf16.bf16.f32 " \
        "{%0,%1,%2,%3}, {%4,%5,%6,%7}, {%8,%9}, {%0,%1,%2,%3};\n" \
        : "+f"(ACC[0]), "+f"(ACC[1]), "+f"(ACC[2]), "+f"(ACC[3]) \
        : "r"(A0), "r"(A1), "r"(A2), "r"(A3), "r"(B0), "r"(B1))

#define LDCG4(V, P) asm volatile("ld.global.cg.v4.u32 {%0,%1,%2,%3}, [%4];" \
    : "=r"(V.x), "=r"(V.y), "=r"(V.z), "=r"(V.w) : "l"(P))
#define STCG32(P, V) asm volatile("st.global.cg.u32 [%0], %1;" :: "l"(P), "r"(V))

// ================= split-bf16 encoder LSTM scan (256 thr, split-K) =================
__global__ void __launch_bounds__(NT, 1) lstm_scan_split_kernel(
    const float* __restrict__ Whh, const float* __restrict__ gx,
    __nv_bfloat16* __restrict__ hs_hi, __nv_bfloat16* __restrict__ hs_lo)
{
    extern __shared__ __nv_bfloat16 sm[];
    __nv_bfloat16* Wh = sm;
    __nv_bfloat16* Wl = sm + 32 * SPAD;
    __nv_bfloat16* Hh = sm + 64 * SPAD;
    __nv_bfloat16* Hl = sm + 128 * SPAD;
    float4* Sred = (float4*)(sm + 192 * SPAD);   // [4*32][4] float4
    const int tid  = threadIdx.x;
    const int j0   = blockIdx.x * 8;
    const int warp = tid >> 5, lane = tid & 31;
    const int grp  = warp >> 2, wj = warp & 3;
    const int qr   = lane >> 2, qc = lane & 3;
    const int r0   = wj * 16 + qr;
    const int ktb  = grp * 16;

    for (int idx = tid; idx < 32 * 128; idx += NT) {
        int rl = idx >> 7, c4 = (idx & 127) << 2;
        int gi = rl >> 3, jj = rl & 7;
        float4 v = *(const float4*)(Whh + (size_t)(gi * 512 + j0 + jj) * 512 + c4);
        __nv_bfloat16* ph = Wh + rl * SPAD + c4;
        __nv_bfloat16* pl = Wl + rl * SPAD + c4;
        float f[4] = {v.x, v.y, v.z, v.w};
        #pragma unroll
        for (int q = 0; q < 4; ++q) {
            __nv_bfloat16 h = __float2bfloat16_rn(f[q]);
            ph[q] = h;
            pl[q] = __float2bfloat16_rn(f[q] - __bfloat162float(h));
        }
    }
    for (int idx = tid; idx < 512; idx += NT) {
        int r = idx >> 3, jj = idx & 7;
        unsigned short z = 0;
        asm volatile("st.global.cg.u16 [%0], %1;" :: "l"(g_ehi[0] + r * 512 + j0 + jj), "h"(z));
        asm volatile("st.global.cg.u16 [%0], %1;" :: "l"(g_elo[0] + r * 512 + j0 + jj), "h"(z));
    }
    float creg[4] = {0.f, 0.f, 0.f, 0.f};
    float pf[4][4], acc[4][4];
    if (grp == 0) {
        #pragma unroll
        for (int i = 0; i < 4; ++i) {
            int col = i * 512 + j0 + qc * 2;
            float2 lo = *(const float2*)(gx + (size_t)r0       * 2048 + col);
            float2 hi = *(const float2*)(gx + (size_t)(r0 + 8) * 2048 + col);
            pf[i][0] = lo.x; pf[i][1] = lo.y; pf[i][2] = hi.x; pf[i][3] = hi.y;
        }
    }
    unsigned tok = bar_arrive();
    bar_wait(tok);

    for (int t = 0; t < TT; ++t) {
        const __nv_bfloat16* rbh = g_ehi[t & 1];
        const __nv_bfloat16* rbl = g_elo[t & 1];
        __nv_bfloat16* wbh = g_ehi[(t + 1) & 1];
        __nv_bfloat16* wbl = g_elo[(t + 1) & 1];

        for (int idx = tid; idx < 64 * 64; idx += NT) {
            int r = idx >> 6, c8 = (idx & 63) << 3;
            uint4 v;
            LDCG4(v, rbh + r * 512 + c8); *(uint4*)(Hh + r * SPAD + c8) = v;
            LDCG4(v, rbl + r * 512 + c8); *(uint4*)(Hl + r * SPAD + c8) = v;
        }
        __syncthreads();

        #pragma unroll
        for (int i = 0; i < 4; ++i)
            #pragma unroll
            for (int k = 0; k < 4; ++k) acc[i][k] = (grp == 0) ? pf[i][k] : 0.f;

        #pragma unroll
        for (int kt2 = 0; kt2 < 16; ++kt2) {
            const int k0 = (ktb + kt2) * 16 + qc * 2;
            uint32_t ah0 = *(const uint32_t*)(Hh + r0 * SPAD + k0);
            uint32_t ah1 = *(const uint32_t*)(Hh + (r0 + 8) * SPAD + k0);
            uint32_t ah2 = *(const uint32_t*)(Hh + r0 * SPAD + k0 + 8);
            uint32_t ah3 = *(const uint32_t*)(Hh + (r0 + 8) * SPAD + k0 + 8);
            uint32_t al0 = *(const uint32_t*)(Hl + r0 * SPAD + k0);
            uint32_t al1 = *(const uint32_t*)(Hl + (r0 + 8) * SPAD + k0);
            uint32_t al2 = *(const uint32_t*)(Hl + r0 * SPAD + k0 + 8);
            uint32_t al3 = *(const uint32_t*)(Hl + (r0 + 8) * SPAD + k0 + 8);
            #pragma unroll
            for (int i = 0; i < 4; ++i) {
                uint32_t bh0 = *(const uint32_t*)(Wh + (i * 8 + qr) * SPAD + k0);
                uint32_t bh1 = *(const uint32_t*)(Wh + (i * 8 + qr) * SPAD + k0 + 8);
                uint32_t bl0 = *(const uint32_t*)(Wl + (i * 8 + qr) * SPAD + k0);
                uint32_t bl1 = *(const uint32_t*)(Wl + (i * 8 + qr) * SPAD + k0 + 8);
                MMA_BF16(acc[i], ah0, ah1, ah2, ah3, bh0, bh1);
                MMA_BF16(acc[i], ah0, ah1, ah2, ah3, bl0, bl1);
                MMA_BF16(acc[i], al0, al1, al2, al3, bh0, bh1);
            }
        }
        __syncthreads();
        if (grp == 1) {
            int base = (wj * 32 + lane) * 4;
            #pragma unroll
            for (int i = 0; i < 4; ++i)
                Sred[base + i] = make_float4(acc[i][0], acc[i][1], acc[i][2], acc[i][3]);
        }
        __syncthreads();
        if (grp == 0) {
            int base = (wj * 32 + lane) * 4;
            #pragma unroll
            for (int i = 0; i < 4; ++i) {
                float4 p = Sred[base + i];
                acc[i][0] += p.x; acc[i][1] += p.y; acc[i][2] += p.z; acc[i][3] += p.w;
            }
            float hv[4];
            #pragma unroll
            for (int k = 0; k < 4; ++k) {
                float ig = fsig(acc[0][k]);
                float fg = fsig(acc[1][k]);
                float gg = ftanhx(acc[2][k]);
                float og = fsig(acc[3][k]);
                creg[k] = fg * creg[k] + ig * gg;
                hv[k]   = og * ftanhx(creg[k]);
            }
            __nv_bfloat16 hh[4], hl[4];
            #pragma unroll
            for (int k = 0; k < 4; ++k) {
                hh[k] = __float2bfloat16_rn(hv[k]);
                hl[k] = __float2bfloat16_rn(hv[k] - __bfloat162float(hh[k]));
            }
            uint32_t ph0 = ((uint32_t)*(unsigned short*)&hh[1] << 16) | *(unsigned short*)&hh[0];
            uint32_t ph1 = ((uint32_t)*(unsigned short*)&hh[3] << 16) | *(unsigned short*)&hh[2];
            uint32_t pl0 = ((uint32_t)*(unsigned short*)&hl[1] << 16) | *(unsigned short*)&hl[0];
            uint32_t pl1 = ((uint32_t)*(unsigned short*)&hl[3] << 16) | *(unsigned short*)&hl[2];
            const int cb = j0 + qc * 2;
            STCG32(wbh + r0 * 512 + cb, ph0);
            STCG32(wbh + (r0 + 8) * 512 + cb, ph1);
            STCG32(wbl + r0 * 512 + cb, pl0);
            STCG32(wbl + (r0 + 8) * 512 + cb, pl1);
            if (hs_hi) {
                *(uint32_t*)(hs_hi + (size_t)(t * 64 + r0)     * 512 + cb) = ph0;
                *(uint32_t*)(hs_hi + (size_t)(t * 64 + r0 + 8) * 512 + cb) = ph1;
                *(uint32_t*)(hs_lo + (size_t)(t * 64 + r0)     * 512 + cb) = pl0;
                *(uint32_t*)(hs_lo + (size_t)(t * 64 + r0 + 8) * 512 + cb) = pl1;
            }
        }
        tok = bar_arrive();
        if (grp == 0 && t + 1 < TT) {
            #pragma unroll
            for (int i = 0; i < 4; ++i) {
                int col = i * 512 + j0 + qc * 2;
                float2 lo = *(const float2*)(gx + (size_t)((t + 1) * 64 + r0)     * 2048 + col);
                float2 hi = *(const float2*)(gx + (size_t)((t + 1) * 64 + r0 + 8) * 2048 + col);
                pf[i][0] = lo.x; pf[i][1] = lo.y; pf[i][2] = hi.x; pf[i][3] = hi.y;
            }
        }
        bar_wait(tok);
    }
}

// ================= plain bf16 decoder LSTM scan (256 thr, split-K) =================
__global__ void __launch_bounds__(NT, 1) lstm_scan_kernel(
    const __nv_bfloat16* __restrict__ Whh, const float* __restrict__ gx,
    const float* __restrict__ bias, const float* __restrict__ h0,
    __nv_bfloat16* __restrict__ hs)
{
    extern __shared__ __nv_bfloat16 sm[];
    __nv_bfloat16* Ws = sm;
    __nv_bfloat16* Hb = sm + 32 * SPAD;
    float4* Sred = (float4*)(sm + 96 * SPAD);
    const int tid  = threadIdx.x;
    const int j0   = blockIdx.x * 8;
    const int warp = tid >> 5, lane = tid & 31;
    const int grp  = warp >> 2, wj = warp & 3;
    const int qr   = lane >> 2, qc = lane & 3;
    const int r0   = wj * 16 + qr;
    const int ktb  = grp * 16;

    for (int idx = tid; idx < 32 * 64; idx += NT) {
        int rl = idx >> 6, c8 = (idx & 63) << 3;
        int gi = rl >> 3, jj = rl & 7;
        *(uint4*)(Ws + rl * SPAD + c8) =
            *(const uint4*)(Whh + (size_t)(gi * 512 + j0 + jj) * 512 + c8);
    }
    for (int idx = tid; idx < 512; idx += NT) {
        int r = idx >> 3, jj = idx & 7;
        float v = h0 ? h0[r * 512 + j0 + jj] : 0.f;
        __nv_bfloat16 bv = __float2bfloat16(v);
        unsigned short us = *(unsigned short*)&bv;
        asm volatile("st.global.cg.u16 [%0], %1;" :: "l"(g_hcur[0] + r * 512 + j0 + jj), "h"(us));
    }
    float creg[4] = {0.f, 0.f, 0.f, 0.f};
    float pf[4][4], acc[4][4];
    if (grp == 0) {
        #pragma unroll
        for (int i = 0; i < 4; ++i) {
            int col = i * 512 + j0 + qc * 2;
            if (gx) {
                float2 lo = *(const float2*)(gx + (size_t)r0       * 2048 + col);
                float2 hi = *(const float2*)(gx + (size_t)(r0 + 8) * 2048 + col);
                pf[i][0] = lo.x; pf[i][1] = lo.y; pf[i][2] = hi.x; pf[i][3] = hi.y;
            } else {
                float b0v = bias[col], b1v = bias[col + 1];
                pf[i][0] = b0v; pf[i][1] = b1v; pf[i][2] = b0v; pf[i][3] = b1v;
            }
        }
    }
    unsigned tok = bar_arrive();
    bar_wait(tok);

    for (int t = 0; t < TT; ++t) {
        const __nv_bfloat16* rb = g_hcur[t & 1];
        __nv_bfloat16*       wb = g_hcur[(t + 1) & 1];

        for (int idx = tid; idx < 64 * 64; idx += NT) {
            int r = idx >> 6, c8 = (idx & 63) << 3;
            uint4 v;
            LDCG4(v, rb + r * 512 + c8);
            *(uint4*)(Hb + r * SPAD + c8) = v;
        }
        __syncthreads();

        #pragma unroll
        for (int i = 0; i < 4; ++i)
            #pragma unroll
            for (int k = 0; k < 4; ++k) acc[i][k] = (grp == 0) ? pf[i][k] : 0.f;

        #pragma unroll
        for (int kt2 = 0; kt2 < 16; ++kt2) {
            const int k0 = (ktb + kt2) * 16 + qc * 2;
            uint32_t a0 = *(const uint32_t*)(Hb + r0 * SPAD + k0);
            uint32_t a1 = *(const uint32_t*)(Hb + (r0 + 8) * SPAD + k0);
            uint32_t a2 = *(const uint32_t*)(Hb + r0 * SPAD + k0 + 8);
            uint32_t a3 = *(const uint32_t*)(Hb + (r0 + 8) * SPAD + k0 + 8);
            #pragma unroll
            for (int i = 0; i < 4; ++i) {
                uint32_t b0 = *(const uint32_t*)(Ws + (i * 8 + qr) * SPAD + k0);
                uint32_t b1 = *(const uint32_t*)(Ws + (i * 8 + qr) * SPAD + k0 + 8);
                MMA_BF16(acc[i], a0, a1, a2, a3, b0, b1);
            }
        }
        __syncthreads();
        if (grp == 1) {
            int base = (wj * 32 + lane) * 4;
            #pragma unroll
            for (int i = 0; i < 4; ++i)
                Sred[base + i] = make_float4(acc[i][0], acc[i][1], acc[i][2], acc[i][3]);
        }
        __syncthreads();
        if (grp == 0) {
            int base = (wj * 32 + lane) * 4;
            #pragma unroll
            for (int i = 0; i < 4; ++i) {
                float4 p = Sred[base + i];
                acc[i][0] += p.x; acc[i][1] += p.y; acc[i][2] += p.z; acc[i][3] += p.w;
            }
            float hv[4];
            #pragma unroll
            for (int k = 0; k < 4; ++k) {
                float ig = fsig(acc[0][k]);
                float fg = fsig(acc[1][k]);
                float gg = ftanhx(acc[2][k]);
                float og = fsig(acc[3][k]);
                creg[k] = fg * creg[k] + ig * gg;
                hv[k]   = og * ftanhx(creg[k]);
            }
            __nv_bfloat162 p0 = __floats2bfloat162_rn(hv[0], hv[1]);
            __nv_bfloat162 p1 = __floats2bfloat162_rn(hv[2], hv[3]);
            const int cb = j0 + qc * 2;
            STCG32(wb + r0 * 512 + cb, *(uint32_t*)&p0);
            STCG32(wb + (r0 + 8) * 512 + cb, *(uint32_t*)&p1);
            if (hs) {
                *(__nv_bfloat162*)(hs + (size_t)(t * 64 + r0)     * 512 + cb) = p0;
                *(__nv_bfloat162*)(hs + (size_t)(t * 64 + r0 + 8) * 512 + cb) = p1;
            }
        }
        tok = bar_arrive();
        if (grp == 0 && gx && t + 1 < TT) {
            #pragma unroll
            for (int i = 0; i < 4; ++i) {
                int col = i * 512 + j0 + qc * 2;
                float2 lo = *(const float2*)(gx + (size_t)((t + 1) * 64 + r0)     * 2048 + col);
                float2 hi = *(const float2*)(gx + (size_t)((t + 1) * 64 + r0 + 8) * 2048 + col);
                pf[i][0] = lo.x; pf[i][1] = lo.y; pf[i][2] = hi.x; pf[i][3] = hi.y;
            }
        }
        bar_wait(tok);
    }
}

// ================= split-bf16 GEMM 128x128 tile =================
__global__ void __launch_bounds__(NT, 2) gemm_split_kernel(
    const __nv_bfloat16* __restrict__ Ah, const __nv_bfloat16* __restrict__ Al,
    const __nv_bfloat16* __restrict__ Bh, const __nv_bfloat16* __restrict__ Bl,
    const float* __restrict__ bias, float* __restrict__ Cout, int N, int K)
{
    __shared__ __nv_bfloat16 Ash[128 * 40];
    __shared__ __nv_bfloat16 Asl[128 * 40];
    __shared__ __nv_bfloat16 Bsh[128 * 40];
    __shared__ __nv_bfloat16 Bsl[128 * 40];
    const int tid  = threadIdx.x;
    const int warp = tid >> 5, lane = tid & 31;
    const int qr   = lane >> 2, qc = lane & 3;
    const int wm   = warp >> 2, wn = warp & 3;
    const int m0   = blockIdx.x * 128;
    const int n0   = blockIdx.y * 128;

    float acc[4][4][4];
    #pragma unroll
    for (int a = 0; a < 4; ++a)
        #pragma unroll
        for (int b = 0; b < 4; ++b)
            #pragma unroll
            for (int c = 0; c < 4; ++c) acc[a][b][c] = 0.f;

    for (int kt = 0; kt < K; kt += 32) {
        #pragma unroll
        for (int u = 0; u < 2; ++u) {
            int idx = tid + u * 256;
            int r = idx >> 2, c8 = (idx & 3) << 3;
            *(uint4*)(Ash + r * 40 + c8) = *(const uint4*)(Ah + (size_t)(m0 + r) * K + kt + c8);
            *(uint4*)(Asl + r * 40 + c8) = *(const uint4*)(Al + (size_t)(m0 + r) * K + kt + c8);
            *(uint4*)(Bsh + r * 40 + c8) = *(const uint4*)(Bh + (size_t)(n0 + r) * K + kt + c8);
            *(uint4*)(Bsl + r * 40 + c8) = *(const uint4*)(Bl + (size_t)(n0 + r) * K + kt + c8);
        }
        __syncthreads();
        #pragma unroll
        for (int kk = 0; kk < 2; ++kk) {
            const int k0 = kk * 16 + qc * 2;
            #pragma unroll
            for (int mi = 0; mi < 4; ++mi) {
                int ar = wm * 64 + mi * 16 + qr;
                uint32_t ah0 = *(const uint32_t*)(Ash + ar * 40 + k0);
                uint32_t ah1 = *(const uint32_t*)(Ash + (ar + 8) * 40 + k0);
                uint32_t ah2 = *(const uint32_t*)(Ash + ar * 40 + k0 + 8);
                uint32_t ah3 = *(const uint32_t*)(Ash + (ar + 8) * 40 + k0 + 8);
                uint32_t al0 = *(const uint32_t*)(Asl + ar * 40 + k0);
                uint32_t al1 = *(const uint32_t*)(Asl + (ar + 8) * 40 + k0);
                uint32_t al2 = *(const uint32_t*)(Asl + ar * 40 + k0 + 8);
                uint32_t al3 = *(const uint32_t*)(Asl + (ar + 8) * 40 + k0 + 8);
                #pragma unroll
                for (int ni = 0; ni < 4; ++ni) {
                    int br = wn * 32 + ni * 8 + qr;
                    uint32_t bh0 = *(const uint32_t*)(Bsh + br * 40 + k0);
                    uint32_t bh1 = *(const uint32_t*)(Bsh + br * 40 + k0 + 8);
                    uint32_t bl0 = *(const uint32_t*)(Bsl + br * 40 + k0);
                    uint32_t bl1 = *(const uint32_t*)(Bsl + br * 40 + k0 + 8);
                    MMA_BF16(acc[mi][ni], ah0, ah1, ah2, ah3, bh0, bh1);
                    MMA_BF16(acc[mi][ni], ah0, ah1, ah2, ah3, bl0, bl1);
                    MMA_BF16(acc[mi][ni], al0, al1, al2, al3, bh0, bh1);
                }
            }
        }
        __syncthreads();
    }
    #pragma unroll
    for (int mi = 0; mi < 4; ++mi)
        #pragma unroll
        for (int ni = 0; ni < 4; ++ni) {
            int gn = n0 + wn * 32 + ni * 8 + qc * 2;
            float bv0 = bias[gn], bv1 = bias[gn + 1];
            #pragma unroll
            for (int h = 0; h < 2; ++h) {
                int gm = m0 + wm * 64 + mi * 16 + qr + h * 8;
                *(float2*)(Cout + (size_t)gm * N + gn) =
                    make_float2(acc[mi][ni][h * 2 + 0] + bv0, acc[mi][ni][h * 2 + 1] + bv1);
            }
        }
}

// ================= plain bf16 GEMM 128x128 tile =================
__global__ void __launch_bounds__(NT, 2) gemm_bf16_kernel(
    const __nv_bfloat16* __restrict__ A, const __nv_bfloat16* __restrict__ Bw,
    const float* __restrict__ bias, float* __restrict__ Cout, int N, int K, int mode)
{
    __shared__ __nv_bfloat16 As[128 * 40];
    __shared__ __nv_bfloat16 Bs[128 * 40];
    const int tid  = threadIdx.x;
    const int warp = tid >> 5, lane = tid & 31;
    const int qr   = lane >> 2, qc = lane & 3;
    const int wm   = warp >> 2, wn = warp & 3;
    const int m0   = blockIdx.x * 128;
    const int n0   = blockIdx.y * 128;

    float acc[4][4][4];
    #pragma unroll
    for (int a = 0; a < 4; ++a)
        #pragma unroll
        for (int b = 0; b < 4; ++b)
            #pragma unroll
            for (int c = 0; c < 4; ++c) acc[a][b][c] = 0.f;

    for (int kt = 0; kt < K; kt += 32) {
        #pragma unroll
        for (int u = 0; u < 2; ++u) {
            int idx = tid + u * 256;
            int r = idx >> 2, c8 = (idx & 3) << 3;
            *(uint4*)(As + r * 40 + c8) = *(const uint4*)(A + (size_t)(m0 + r) * K + kt + c8);
            *(uint4*)(Bs + r * 40 + c8) = *(const uint4*)(Bw + (size_t)(n0 + r) * K + kt + c8);
        }
        __syncthreads();
        #pragma unroll
        for (int kk = 0; kk < 2; ++kk) {
            const int k0 = kk * 16 + qc * 2;
            #pragma unroll
            for (int mi = 0; mi < 4; ++mi) {
                int ar = wm * 64 + mi * 16 + qr;
                uint32_t a0 = *(const uint32_t*)(As + ar * 40 + k0);
                uint32_t a1 = *(const uint32_t*)(As + (ar + 8) * 40 + k0);
                uint32_t a2 = *(const uint32_t*)(As + ar * 40 + k0 + 8);
                uint32_t a3 = *(const uint32_t*)(As + (ar + 8) * 40 + k0 + 8);
                #pragma unroll
                for (int ni = 0; ni < 4; ++ni) {
                    int br = wn * 32 + ni * 8 + qr;
                    uint32_t b0 = *(const uint32_t*)(Bs + br * 40 + k0);
                    uint32_t b1 = *(const uint32_t*)(Bs + br * 40 + k0 + 8);
                    MMA_BF16(acc[mi][ni], a0, a1, a2, a3, b0, b1);
                }
            }
        }
        __syncthreads();
    }
    #pragma unroll
    for (int mi = 0; mi < 4; ++mi)
        #pragma unroll
        for (int ni = 0; ni < 4; ++ni) {
            int gn = n0 + wn * 32 + ni * 8 + qc * 2;
            float bv0 = bias[gn], bv1 = bias[gn + 1];
            #pragma unroll
            for (int h = 0; h < 2; ++h) {
                int gm = m0 + wm * 64 + mi * 16 + qr + h * 8;
                float v0 = acc[mi][ni][h * 2 + 0] + bv0;
                float v1 = acc[mi][ni][h * 2 + 1] + bv1;
                if (mode == 1) {
                    int tt = gm >> 6, bb = gm & 63;
                    *(float2*)(Cout + ((size_t)bb * TT + tt) * DD + gn) =
                        make_float2(fsig(v0), fsig(v1));
                } else {
                    *(float2*)(Cout + (size_t)gm * N + gn) = make_float2(v0, v1);
                }
            }
        }
}

// ================= fused prep kernels =================
__global__ void prep_weights_kernel(
    const float* __restrict__ eWih0, const float* __restrict__ eWih1,
    const float* __restrict__ dWhh0, const float* __restrict__ dWih1,
    const float* __restrict__ dWhh1, const float* __restrict__ opW)
{
    int i = blockIdx.x * blockDim.x + threadIdx.x;
    int task = blockIdx.y;
    if (task == 0) {
        if (i < G4 * DD) {
            float v = eWih0[i];
            __nv_bfloat16 h = __float2bfloat16_rn(v);
            g_wih0h[i] = h;
            g_wih0l[i] = __float2bfloat16_rn(v - __bfloat162float(h));
        }
    } else if (task == 1) {
        if (i < G4 * HH) {
            float v = eWih1[i];
            __nv_bfloat16 h = __float2bfloat16_rn(v);
            g_wih1h[i] = h;
            g_wih1l[i] = __float2bfloat16_rn(v - __bfloat162float(h));
        }
    } else if (task == 2) { if (i < G4 * HH) g_whh[0][i] = __float2bfloat16(dWhh0[i]); }
    else if (task == 3)   { if (i < G4 * HH) g_wih1d[i] = __float2bfloat16(dWih1[i]); }
    else if (task == 4)   { if (i < G4 * HH) g_whh[1][i] = __float2bfloat16(dWhh1[i]); }
    else                  { if (i < DD * HH) g_opw[i] = __float2bfloat16(opW[i]); }
}

__global__ void prep_misc_kernel(
    const float* __restrict__ x,
    const float* __restrict__ b0a, const float* __restrict__ b0b,
    const float* __restrict__ b1a, const float* __restrict__ b1b,
    const float* __restrict__ b2a, const float* __restrict__ b2b,
    const float* __restrict__ b3a, const float* __restrict__ b3b)
{
    int i = blockIdx.x * blockDim.x + threadIdx.x;
    if (i < 4 * G4) {
        int l = i >> 11, j = i & (G4 - 1);
        const float* pa = (l == 0) ? b0a : (l == 1) ? b1a : (l == 2) ? b2a : b3a;
        const float* pb = (l == 0) ? b0b : (l == 1) ? b1b : (l == 2) ? b2b : b3b;
        g_bsum[l][j] = pa[j] + pb[j];
    }
    if (i < TB * DD) {
        int d = i & (DD - 1);
        int r = i >> 7;
        int b = r & 63, t = r >> 6;
        float v = x[((size_t)b * TT + t) * DD + d];
        __nv_bfloat16 h = __float2bfloat16_rn(v);
        g_xth[i] = h;
        g_xtl[i] = __float2bfloat16_rn(v - __bfloat162float(h));
    }
}

__global__ void z_kernel(const float* __restrict__ tlW, const float* __restrict__ tlb,
                         float* __restrict__ zout) {
    int idx = blockIdx.x * blockDim.x + threadIdx.x;
    if (idx < BB * ZZ) {
        int b = idx >> 6, j = idx & 63;
        float s = 0.f;
        for (int k = 0; k < 512; ++k) {
            float hv = __bfloat162float(g_ehi[0][b * 512 + k]) +
                       __bfloat162float(g_elo[0][b * 512 + k]);
            s += hv * tlW[j * 512 + k];
        }
        s += tlb[j];
        g_zbuf[idx] = s;
        zout[idx] = s;
    }
}
__global__ void m_kernel(const float* __restrict__ lhW, const float* __restrict__ lhb) {
    int b = blockIdx.x, k1 = threadIdx.x;
    float s = 0.f;
    for (int j = 0; j < 64; ++j)
        s += g_zbuf[b * 64 + j] * lhW[k1 * 64 + j];
    g_M[b * 1024 + k1] = tanhf(s + lhb[k1]);
}

extern "C" void kernel_launch(void* const* d_in, const int* in_sizes, int n_in,
                              void* d_out, int out_size) {
    const float* x     = (const float*)d_in[0];
    const float* eWih0 = (const float*)d_in[1];
    const float* eWhh0 = (const float*)d_in[2];
    const float* ebih0 = (const float*)d_in[3];
    const float* ebhh0 = (const float*)d_in[4];
    const float* eWih1 = (const float*)d_in[5];
    const float* eWhh1 = (const float*)d_in[6];
    const float* ebih1 = (const float*)d_in[7];
    const float* ebhh1 = (const float*)d_in[8];
    const float* dWhh0 = (const float*)d_in[10];
    const float* dbih0 = (const float*)d_in[11];
    const float* dbhh0 = (const float*)d_in[12];
    const float* dWih1 = (const float*)d_in[13];
    const float* dWhh1 = (const float*)d_in[14];
    const float* dbih1 = (const float*)d_in[15];
    const float* dbhh1 = (const float*)d_in[16];
    const float* tlW   = (const float*)d_in[17];
    const float* tlb   = (const float*)d_in[18];
    const float* lhW   = (const float*)d_in[19];
    const float* lhb   = (const float*)d_in[20];
    const float* opW   = (const float*)d_in[21];
    const float* opb   = (const float*)d_in[22];
    float* out = (float*)d_out;

    __nv_bfloat16 *p_xth, *p_xtl, *p_whh0, *p_whh1;
    __nv_bfloat16 *p_w0h, *p_w0l, *p_w1h, *p_w1l, *p_wih1d, *p_opw;
    __nv_bfloat16 *p_hs, *p_hsh, *p_hsl;
    float *p_gx, *p_bs, *p_M;
    cudaGetSymbolAddress((void**)&p_xth, g_xth);
    cudaGetSymbolAddress((void**)&p_xtl, g_xtl);
    cudaGetSymbolAddress((void**)&p_gx, g_gx);
    cudaGetSymbolAddress((void**)&p_hs, g_hs);
    cudaGetSymbolAddress((void**)&p_hsh, g_hsh);
    cudaGetSymbolAddress((void**)&p_hsl, g_hsl);
    cudaGetSymbolAddress((void**)&p_bs, g_bsum);
    cudaGetSymbolAddress((void**)&p_M,  g_M);
    cudaGetSymbolAddress((void**)&p_w0h, g_wih0h);
    cudaGetSymbolAddress((void**)&p_w0l, g_wih0l);
    cudaGetSymbolAddress((void**)&p_w1h, g_wih1h);
    cudaGetSymbolAddress((void**)&p_w1l, g_wih1l);
    cudaGetSymbolAddress((void**)&p_wih1d, g_wih1d);
    cudaGetSymbolAddress((void**)&p_opw, g_opw);
    {
        __nv_bfloat16* base;
        cudaGetSymbolAddress((void**)&base, g_whh);
        p_whh0 = base;
        p_whh1 = base + (size_t)G4 * HH;
    }

    const int SPLIT_SMEM = 192 * SPAD * 2 + 8192;   // 207,872
    const int DEC_SMEM   = 96 * SPAD * 2 + 8192;    // 108,032
    cudaFuncSetAttribute(lstm_scan_split_kernel,
        cudaFuncAttributeMaxDynamicSharedMemorySize, SPLIT_SMEM);
    cudaFuncSetAttribute(lstm_scan_kernel,
        cudaFuncAttributeMaxDynamicSharedMemorySize, DEC_SMEM);

    // launch 0: weights prep
    prep_weights_kernel<<<dim3(4096, 6), 256>>>(eWih0, eWih1, dWhh0, dWih1, dWhh1, opW);
    // launch 1: bias sums + x transpose/split
    prep_misc_kernel<<<TB * DD / 256, 256>>>(x, ebih0, ebhh0, ebih1, ebhh1,
                                             dbih0, dbhh0, dbih1, dbhh1);

    dim3 gemm_grid(TB / 128, G4 / 128);
    // launch 2-3: encoder layer 0
    gemm_split_kernel<<<gemm_grid, NT>>>(p_xth, p_xtl, p_w0h, p_w0l, p_bs + 0*G4, p_gx, G4, DD);
    lstm_scan_split_kernel<<<GCTAS, NT, SPLIT_SMEM>>>(eWhh0, p_gx, p_hsh, p_hsl);
    // launch 4-5: encoder layer 1  (launch 5 = profiled scan)
    gemm_split_kernel<<<gemm_grid, NT>>>(p_hsh, p_hsl, p_w1h, p_w1l, p_bs + 1*G4, p_gx, G4, HH);
    lstm_scan_split_kernel<<<GCTAS, NT, SPLIT_SMEM>>>(eWhh1, p_gx, nullptr, nullptr);
    // latent
    z_kernel<<<(BB * ZZ + 255) / 256, 256>>>(tlW, tlb, out + (size_t)BB * TT * DD);
    m_kernel<<<BB, 1024>>>(lhW, lhb);
    // decoder
    lstm_scan_kernel<<<GCTAS, NT, DEC_SMEM>>>(p_whh0, nullptr, p_bs + 2*G4, p_M, p_hs);
    gemm_bf16_kernel<<<gemm_grid, NT>>>(p_hs, p_wih1d, p_bs + 3*G4, p_gx, G4, HH, 0);
    lstm_scan_kernel<<<GCTAS, NT, DEC_SMEM>>>(p_whh1, p_gx, nullptr, p_M + 32768, p_hs);
    // output projection + sigmoid
    dim3 op_grid(TB / 128, 1);
    gemm_bf16_kernel<<<op_grid, NT>>>(p_hs, p_opw, opb, out, DD, HH, 1);
}